// round 2
// baseline (speedup 1.0000x reference)
#include <cuda_runtime.h>

// Problem constants
#define NTOK (512 * 2048)   // 1,048,576 tokens
#define DIN  20
#define DH   256
#define DOUT 10

#define TPB  256            // threads per block
#define TPT  4              // tokens per thread
#define TOKS_PER_BLOCK (TPB * TPT)          // 1024
#define NBLK (NTOK / TOKS_PER_BLOCK)        // 1024 blocks exactly cover all tokens

// Deterministic reduction scratch (no device allocs allowed)
__device__ float g_psy[NBLK];
__device__ float g_psa[NBLK];

// ---------------------------------------------------------------------------
// Kernel 1: fused MLP + per-block (sum y, sum |y|) partials
// ---------------------------------------------------------------------------
__global__ __launch_bounds__(TPB, 1)
void mlp_main(const float* __restrict__ X,
              const float* __restrict__ W1,   // [DIN, DH] row-major
              const float* __restrict__ b1,   // [DH]
              const float* __restrict__ W2,   // [DH, DOUT] row-major
              const float* __restrict__ b2)   // [DOUT]
{
    // Per hidden unit j: 32 floats = { W1[0..19][j], W2[j][0..9], b1[j], pad }
    __shared__ float wsh[DH * 32];
    __shared__ float b2sh[DOUT];

    const int tid = threadIdx.x;

    for (int j = tid; j < DH; j += TPB) {
        float* row = &wsh[j * 32];
        #pragma unroll
        for (int i = 0; i < DIN; ++i) row[i] = W1[i * DH + j];
        #pragma unroll
        for (int o = 0; o < DOUT; ++o) row[DIN + o] = W2[j * DOUT + o];
        row[30] = b1[j];
        row[31] = 0.0f;
    }
    if (tid < DOUT) b2sh[tid] = b2[tid];
    __syncthreads();

    // Load this thread's 4 tokens (each 20 floats = 5 aligned float4: 80B, 16B-aligned)
    const long base = (long)blockIdx.x * TOKS_PER_BLOCK;
    float x[TPT][DIN];
    #pragma unroll
    for (int t = 0; t < TPT; ++t) {
        const long tok = base + (long)t * TPB + tid;
        const float4* p = reinterpret_cast<const float4*>(X + tok * DIN);
        #pragma unroll
        for (int q = 0; q < DIN / 4; ++q) {
            float4 v = p[q];
            x[t][4 * q + 0] = v.x;
            x[t][4 * q + 1] = v.y;
            x[t][4 * q + 2] = v.z;
            x[t][4 * q + 3] = v.w;
        }
    }

    float acc[TPT][DOUT];
    #pragma unroll
    for (int t = 0; t < TPT; ++t)
        #pragma unroll
        for (int o = 0; o < DOUT; ++o) acc[t][o] = 0.0f;

    // Main loop over hidden units, unrolled x2 so two independent
    // LDS->FFMA dependency chains are in flight per warp.
    // All LDS are warp-uniform (broadcast, conflict-free).
    #pragma unroll 1
    for (int jj = 0; jj < DH; jj += 2) {
        #pragma unroll
        for (int u = 0; u < 2; ++u) {
            const int j = jj + u;
            const float4* wp = reinterpret_cast<const float4*>(&wsh[j * 32]);
            float4 wA = wp[0], wB = wp[1], wC = wp[2], wD = wp[3], wE = wp[4];
            float4 vA = wp[5], vB = wp[6], vC = wp[7];

            const float w1r[DIN] = { wA.x, wA.y, wA.z, wA.w,
                                     wB.x, wB.y, wB.z, wB.w,
                                     wC.x, wC.y, wC.z, wC.w,
                                     wD.x, wD.y, wD.z, wD.w,
                                     wE.x, wE.y, wE.z, wE.w };
            const float w2r[DOUT] = { vA.x, vA.y, vA.z, vA.w,
                                      vB.x, vB.y, vB.z, vB.w,
                                      vC.x, vC.y };
            const float b1j = vC.z;

            #pragma unroll
            for (int t = 0; t < TPT; ++t) {
                float h = b1j;
                #pragma unroll
                for (int i = 0; i < DIN; ++i) h = fmaf(x[t][i], w1r[i], h);
                h = fmaxf(h, 0.0f);
                #pragma unroll
                for (int o = 0; o < DOUT; ++o) acc[t][o] = fmaf(h, w2r[o], acc[t][o]);
            }
        }
    }

    // Per-thread epilogue: add b2, accumulate sum(y) and sum(|y|)
    float sy = 0.0f, sa = 0.0f;
    #pragma unroll
    for (int t = 0; t < TPT; ++t) {
        #pragma unroll
        for (int o = 0; o < DOUT; ++o) {
            float y = acc[t][o] + b2sh[o];
            sy += y;
            sa += fabsf(y);
        }
    }

    // Block reduction (deterministic): warp shuffles + shared
    const int lane = tid & 31;
    const int wid  = tid >> 5;
    #pragma unroll
    for (int off = 16; off > 0; off >>= 1) {
        sy += __shfl_down_sync(0xFFFFFFFFu, sy, off);
        sa += __shfl_down_sync(0xFFFFFFFFu, sa, off);
    }
    __shared__ float rsy[TPB / 32];
    __shared__ float rsa[TPB / 32];
    if (lane == 0) { rsy[wid] = sy; rsa[wid] = sa; }
    __syncthreads();
    if (wid == 0) {
        sy = (lane < TPB / 32) ? rsy[lane] : 0.0f;
        sa = (lane < TPB / 32) ? rsa[lane] : 0.0f;
        #pragma unroll
        for (int off = 4; off > 0; off >>= 1) {
            sy += __shfl_down_sync(0xFFFFFFFFu, sy, off);
            sa += __shfl_down_sync(0xFFFFFFFFu, sa, off);
        }
        if (lane == 0) {
            g_psy[blockIdx.x] = sy;
            g_psa[blockIdx.x] = sa;
        }
    }
}

// ---------------------------------------------------------------------------
// Kernel 2: final reduce (double precision) + halving-count scale
// ---------------------------------------------------------------------------
__global__ __launch_bounds__(TPB)
void mlp_finalize(float* __restrict__ out)
{
    const int tid = threadIdx.x;
    double sy = 0.0, sa = 0.0;
    for (int i = tid; i < NBLK; i += TPB) {
        sy += (double)g_psy[i];
        sa += (double)g_psa[i];
    }
    const int lane = tid & 31;
    const int wid  = tid >> 5;
    #pragma unroll
    for (int off = 16; off > 0; off >>= 1) {
        sy += __shfl_down_sync(0xFFFFFFFFu, sy, off);
        sa += __shfl_down_sync(0xFFFFFFFFu, sa, off);
    }
    __shared__ double dsy[TPB / 32];
    __shared__ double dsa[TPB / 32];
    if (lane == 0) { dsy[wid] = sy; dsa[wid] = sa; }
    __syncthreads();
    if (tid == 0) {
        double tsy = 0.0, tsa = 0.0;
        #pragma unroll
        for (int w = 0; w < TPB / 32; ++w) { tsy += dsy[w]; tsa += dsa[w]; }
        // Replicate: while s > 1: s /= 2; n++;  then out = sum(y) * 2^-n
        int n = 0;
        double s = tsa;
        while (s > 1.0) { s *= 0.5; ++n; }
        out[0] = (float)ldexp(tsy, -n);
    }
}

// ---------------------------------------------------------------------------
// Launch contract
// ---------------------------------------------------------------------------
extern "C" void kernel_launch(void* const* d_in, const int* in_sizes, int n_in,
                              void* d_out, int out_size)
{
    const float* X  = (const float*)d_in[0];
    const float* W1 = (const float*)d_in[1];
    const float* b1 = (const float*)d_in[2];
    const float* W2 = (const float*)d_in[3];
    const float* b2 = (const float*)d_in[4];
    float* out = (float*)d_out;

    mlp_main<<<NBLK, TPB>>>(X, W1, b1, W2, b2);
    mlp_finalize<<<1, TPB>>>(out);
}